// round 8
// baseline (speedup 1.0000x reference)
#include <cuda_runtime.h>
#include <math.h>

#define NB 32
#define NT 512
#define NE 300
#define NH 512
#define NG 2048   // 4*NH

#define NCTA_B 128
#define THR_B  512
#define GRPS   4          // independent batch groups
#define GB     8          // batches per group
#define CPG    32         // CTAs per group
#define JB     16         // j-columns per CTA

#define US2S   34         // u64 per U row (32 used; EVEN -> 16B-aligned pairs)
#define REDR   544        // floats per kt row (8*68)
#define ZSS    68         // zs batch stride

typedef unsigned long long u64;

// ---------------------------------------------------------------------------
__device__ __forceinline__ u64 pack2(float lo, float hi) {
    u64 r; asm("mov.b64 %0, {%1,%2};" : "=l"(r) : "f"(lo), "f"(hi)); return r;
}
__device__ __forceinline__ void fma2(u64& d, u64 a, u64 b) {
    asm("fma.rn.f32x2 %0, %1, %2, %0;" : "+l"(d) : "l"(a), "l"(b));
}
__device__ __forceinline__ float2 unpack2(u64 v) {
    float2 f; asm("mov.b64 {%0,%1}, %2;" : "=f"(f.x), "=f"(f.y) : "l"(v)); return f;
}

__device__ __forceinline__ float fast_sig(float x) {
    float e = __expf(-x);
    return __fdividef(1.f, 1.f + e);
}
__device__ __forceinline__ float fast_tanh(float x) {
    float e = __expf(2.f * x);
    return 1.f - 2.f * __fdividef(1.f, e + 1.f);
}

__device__ __forceinline__ void bar_release_add(unsigned int* p) {
    asm volatile("red.release.gpu.global.add.u32 [%0], %1;"
                 :: "l"(p), "r"(1u) : "memory");
}
__device__ __forceinline__ unsigned int bar_acquire_ld(unsigned int* p) {
    unsigned int v;
    asm volatile("ld.acquire.gpu.global.u32 %0, [%1];"
                 : "=r"(v) : "l"(p) : "memory");
    return v;
}

// Scratch (device globals)
// xz layout: [t][j][b][gate]  (one float4 per (t,j,b))
__device__ float g_xz[(size_t)NT * NH * NB * 4];
// h ping-pong per group: [parity][group][j*8 + b_local]
__device__ float g_h[2][GRPS][NH * GB];
__device__ unsigned int g_bars[GRPS * 32];     // one counter per group, padded

// ---------------------------------------------------------------------------
// Kernel A: z[t][n][b] = sum_k emb[tok(b,t)][k] * W[k][n] + bias[n]
// Tiles 64(M)x64(N), BK=25, f32x2. Also zeroes g_h / g_bars.
// ---------------------------------------------------------------------------
__global__ __launch_bounds__(256) void xz_kernel(
    const int* __restrict__ tokens, const float* __restrict__ emb,
    const float* __restrict__ W, const float* __restrict__ bias)
{
    __shared__ float As[25 * 68];
    __shared__ u64   Bs2[25 * 68];
    __shared__ int   toks[64];

    int tid = threadIdx.x;
    int m0 = blockIdx.y * 64;
    int n0 = blockIdx.x * 64;

    if (blockIdx.x == 0 && blockIdx.y < 32) {
        int i = blockIdx.y * 256 + tid;            // 0..8191 float4
        ((float4*)g_h)[i] = make_float4(0.f, 0.f, 0.f, 0.f);
        if (i < GRPS * 32) g_bars[i] = 0u;
    }

    if (tid < 64) {
        int m = m0 + tid;
        toks[tid] = tokens[(m & 31) * NT + (m >> 5)];
    }
    __syncthreads();

    int tm = tid & 15, tn = tid >> 4;
    u64 acc2[2][4];
    #pragma unroll
    for (int p = 0; p < 2; ++p)
        #pragma unroll
        for (int j = 0; j < 4; ++j) acc2[p][j] = 0ull;

    for (int k0 = 0; k0 < NE; k0 += 25) {
        for (int idx = tid; idx < 64 * 25; idx += 256) {
            int m = idx / 25, kk = idx - m * 25;
            As[kk * 68 + m] = emb[(size_t)toks[m] * NE + k0 + kk];
        }
        for (int idx = tid; idx < 25 * 64; idx += 256) {
            int kk = idx >> 6, n = idx & 63;
            float w = W[(size_t)(k0 + kk) * NG + n0 + n];
            Bs2[kk * 68 + n] = pack2(w, w);
        }
        __syncthreads();

        #pragma unroll
        for (int kk = 0; kk < 25; ++kk) {
            float4 av = *(const float4*)&As[kk * 68 + tm * 4];
            ulonglong2 b01 = *(const ulonglong2*)&Bs2[kk * 68 + tn * 4];
            ulonglong2 b23 = *(const ulonglong2*)&Bs2[kk * 68 + tn * 4 + 2];
            u64 ap[2] = { pack2(av.x, av.y), pack2(av.z, av.w) };
            u64 bd[4] = { b01.x, b01.y, b23.x, b23.y };
            #pragma unroll
            for (int p = 0; p < 2; ++p)
                #pragma unroll
                for (int j = 0; j < 4; ++j)
                    fma2(acc2[p][j], ap[p], bd[j]);
        }
        __syncthreads();
    }

    #pragma unroll
    for (int j = 0; j < 4; ++j) {
        int n = n0 + tn * 4 + j;
        int gate = n >> 9, col = n & 511;
        float bb = bias[n];
        #pragma unroll
        for (int p = 0; p < 2; ++p) {
            float2 v = unpack2(acc2[p][j]);
            int mi0 = m0 + tm * 4 + p * 2;
            int t0 = mi0 >> 5, b0 = mi0 & 31;
            int t1 = (mi0 + 1) >> 5, b1 = (mi0 + 1) & 31;
            __stcs(&g_xz[(((size_t)t0 * NH + col) * NB + b0) * 4 + gate], v.x + bb);
            __stcs(&g_xz[(((size_t)t1 * NH + col) * NB + b1) * 4 + gate], v.y + bb);
        }
    }
}

// ---------------------------------------------------------------------------
// Kernel B: persistent LSTM. 4 independent groups x 32 CTAs. CTA = (group g,
// j-block of 16). U slice 512x64 cols as natural f32x2 pairs. Lane tile
// 8b x 8c, 4-way in-warp K-split (shfl reduce) x 16 warps (smem reduce).
// ---------------------------------------------------------------------------
__global__ __launch_bounds__(THR_B) void lstm_kernel(
    const float* __restrict__ U, float* __restrict__ out)
{
    extern __shared__ float sm[];
    u64*   us2 = (u64*)sm;                      // [512][US2S]
    float* hs  = (float*)(us2 + NH * US2S);     // [512*8]  (== g_h slice layout)
    float* red = hs + NH * GB;                  // [16][REDR]
    float* zs  = red + 16 * REDR;               // [8][ZSS]
    float* cs  = zs + GB * ZSS;                 // [128]

    int tid = threadIdx.x;
    int g    = blockIdx.x >> 5;                 // group 0..3
    int jblk = blockIdx.x & 31;
    int j0 = jblk * JB;

    // Load U slice as natural pairs: c = gate*16 + jj -> U[k][gate*512 + j0 + jj]
    for (int idx = tid; idx < NH * 32; idx += THR_B) {
        int k = idx >> 5, cp = idx & 31;
        int c0 = cp * 2;
        int col = (c0 >> 4) * NH + j0 + (c0 & 15);
        const float* up = &U[(size_t)k * NG + col];
        us2[k * US2S + cp] = pack2(up[0], up[1]);
    }
    if (tid < 128) cs[tid] = 0.f;
    __syncthreads();

    int kt = tid >> 5;                          // warp id = outer K-split (16)
    int lane = tid & 31;
    int ct = lane & 7;                          // c-tile: cols ct*8..ct*8+7
    int ks = lane >> 3;                         // inner K-split (4)
    int cp0 = ct * 4;                           // first u64 col pair (even)
    int jj = tid >> 3, bl = tid & 7;            // gates mapping (tid<128)
    unsigned int* bar = &g_bars[g * 32];

    float4* hs4 = (float4*)hs;

    for (int t = 0; t < NT; ++t) {
        int parity = t & 1;

        // Prefetch xz (coalesced float4 per (j,b_local))
        float4 xv = make_float4(0.f, 0.f, 0.f, 0.f);
        if (tid < 128)
            xv = __ldcs((const float4*)&g_xz[(((size_t)t * NH + j0 + jj) * NB + g * GB + bl) * 4]);

        // Copy group h (16 KB) from global: layouts identical -> direct
        const float4* gh4 = (const float4*)g_h[parity][g];
        hs4[tid]       = __ldcg(gh4 + tid);
        hs4[tid + 512] = __ldcg(gh4 + tid + 512);
        __syncthreads();

        // GEMM: k = kt*32 + ks*8 + i, lane tile 8b x 8c
        u64 acc2[8][4];
        #pragma unroll
        for (int b = 0; b < 8; ++b)
            #pragma unroll
            for (int c = 0; c < 4; ++c) acc2[b][c] = 0ull;

        int kb = kt * 32 + ks * 8;
        #pragma unroll
        for (int i = 0; i < 8; ++i) {
            int k = kb + i;
            float4 h01 = *(const float4*)(hs + k * 8);
            float4 h23 = *(const float4*)(hs + k * 8 + 4);
            const u64* urow = us2 + k * US2S + cp0;
            ulonglong2 ua = *(const ulonglong2*)urow;
            ulonglong2 ub = *(const ulonglong2*)(urow + 2);
            u64 up[4] = { ua.x, ua.y, ub.x, ub.y };
            u64 hp[8] = { pack2(h01.x, h01.x), pack2(h01.y, h01.y),
                          pack2(h01.z, h01.z), pack2(h01.w, h01.w),
                          pack2(h23.x, h23.x), pack2(h23.y, h23.y),
                          pack2(h23.z, h23.z), pack2(h23.w, h23.w) };
            #pragma unroll
            for (int b = 0; b < 8; ++b)
                #pragma unroll
                for (int c = 0; c < 4; ++c)
                    fma2(acc2[b][c], hp[b], up[c]);
        }

        // In-warp reduce over ks (xor 8, 16), then lanes ks==0 store to red
        #pragma unroll
        for (int b = 0; b < 8; ++b) {
            float2 rv[4];
            #pragma unroll
            for (int c = 0; c < 4; ++c) {
                float2 v = unpack2(acc2[b][c]);
                v.x += __shfl_xor_sync(0xffffffffu, v.x, 8);
                v.y += __shfl_xor_sync(0xffffffffu, v.y, 8);
                v.x += __shfl_xor_sync(0xffffffffu, v.x, 16);
                v.y += __shfl_xor_sync(0xffffffffu, v.y, 16);
                rv[c] = v;
            }
            if (ks == 0) {
                float* dst = red + kt * REDR + b * ZSS + ct * 8;
                *(float4*)dst       = make_float4(rv[0].x, rv[0].y, rv[1].x, rv[1].y);
                *(float4*)(dst + 4) = make_float4(rv[2].x, rv[2].y, rv[3].x, rv[3].y);
            }
        }
        __syncthreads();

        // Cross-warp reduce: 512 outputs, 1 per thread
        {
            int b = tid >> 6, c = tid & 63;
            float s = 0.f;
            #pragma unroll
            for (int q = 0; q < 16; ++q) s += red[q * REDR + b * ZSS + c];
            zs[b * ZSS + c] = s;
        }
        __syncthreads();

        // Gates + state update: thread = (jj 0..15, bl 0..7)
        if (tid < 128) {
            float zi = zs[bl * ZSS +  0 + jj] + xv.x;
            float zf = zs[bl * ZSS + 16 + jj] + xv.y;
            float zg = zs[bl * ZSS + 32 + jj] + xv.z;
            float zo = zs[bl * ZSS + 48 + jj] + xv.w;

            float ig = fast_sig(zi);
            float fg = fast_sig(zf);
            float gg = fast_tanh(zg);
            float og = fast_sig(zo);

            float cn = fg * cs[tid] + ig * gg;
            cs[tid] = cn;
            float hn = og * fast_tanh(cn);

            if (t == NT - 1) {
                int bg = g * GB + bl;
                out[bg * NH + (j0 + jj)] = hn;             // hidden [B,H]
                out[NB * NH + bg * NH + (j0 + jj)] = cn;   // cell   [B,H]
            } else {
                __stcg(&g_h[parity ^ 1][g][(j0 + jj) * 8 + bl], hn);
            }
        }

        // Group barrier (32 CTAs): release-increment, acquire-poll (+ backoff)
        if (t < NT - 1) {
            __syncthreads();
            if (tid == 0) {
                bar_release_add(bar);
                unsigned target = (unsigned)CPG * (unsigned)(t + 1);
                while (bar_acquire_ld(bar) < target) {
                    __nanosleep(64);
                }
            }
            __syncthreads();
        }
    }
}

// ---------------------------------------------------------------------------
extern "C" void kernel_launch(void* const* d_in, const int* in_sizes, int n_in,
                              void* d_out, int out_size) {
    const int*   tokens = (const int*)d_in[0];
    const float* emb    = (const float*)d_in[1];
    const float* W      = (const float*)d_in[2];
    const float* U      = (const float*)d_in[3];
    const float* bias   = (const float*)d_in[4];
    float* out = (float*)d_out;

    dim3 ga(NG / 64, (NB * NT) / 64);   // (32, 256)
    xz_kernel<<<ga, 256>>>(tokens, emb, W, bias);

    int smem = (int)(NH * US2S * sizeof(u64) +
                     (NH * GB + 16 * REDR + GB * ZSS + 128) * sizeof(float));
    cudaFuncSetAttribute(lstm_kernel, cudaFuncAttributeMaxDynamicSharedMemorySize, smem);
    lstm_kernel<<<NCTA_B, THR_B, smem>>>(U, out);
}